// round 14
// baseline (speedup 1.0000x reference)
#include <cuda_runtime.h>
#include <cuda_fp16.h>
#include <cstddef>

#define SEQ 2048
#define BATCH 8
#define DMODEL 256
#define NHEADS 8
#define DPROJ 128
#define DFF 1024
#define DH 16
#define MROWS (SEQ*BATCH)   // 16384

// ---------------- scratch (device globals; no allocations allowed) -----------
__device__ __half g_q16[(size_t)MROWS * DPROJ];
__device__ __half g_k16[(size_t)MROWS * DPROJ];
__device__ __half g_v16[(size_t)MROWS * DPROJ];
__device__ __half g_ctx16[(size_t)MROWS * DPROJ];
__device__ __half g_h16[(size_t)MROWS * DFF];
__device__ __half g_x16[(size_t)MROWS * DMODEL];
__device__ __half g_src16[(size_t)MROWS * DMODEL];
__device__ float  g_x[(size_t)MROWS * DMODEL];
__device__ __half g_wq16[DMODEL * DPROJ];
__device__ __half g_wk16[DMODEL * DPROJ];
__device__ __half g_wv16[DMODEL * DPROJ];
__device__ __half g_wo16[DPROJ * DMODEL];
__device__ __half g_w116[DMODEL * DFF];
__device__ __half g_w216[DFF * DMODEL];

// ---------------- PTX helpers ------------------------------------------------
__device__ __forceinline__ unsigned smem_u32(const void* p) {
    return (unsigned)__cvta_generic_to_shared(p);
}
__device__ __forceinline__ void cp16(unsigned dst, const void* src) {
    asm volatile("cp.async.cg.shared.global [%0], [%1], 16;\n" :: "r"(dst), "l"(src));
}
__device__ __forceinline__ void cp_commit() {
    asm volatile("cp.async.commit_group;\n" ::);
}
__device__ __forceinline__ void cp_wait1() {
    asm volatile("cp.async.wait_group 1;\n" ::);
}
__device__ __forceinline__ void cp_wait0() {
    asm volatile("cp.async.wait_group 0;\n" ::);
}
__device__ __forceinline__ unsigned lds_u32(unsigned a) {
    unsigned v;
    asm volatile("ld.shared.u32 %0, [%1];\n" : "=r"(v) : "r"(a));
    return v;
}
__device__ __forceinline__ void ldmx4(unsigned& r0, unsigned& r1, unsigned& r2, unsigned& r3, unsigned a) {
    asm volatile("ldmatrix.sync.aligned.m8n8.x4.shared.b16 {%0,%1,%2,%3}, [%4];\n"
                 : "=r"(r0), "=r"(r1), "=r"(r2), "=r"(r3) : "r"(a));
}
__device__ __forceinline__ void ldmx4t(unsigned& r0, unsigned& r1, unsigned& r2, unsigned& r3, unsigned a) {
    asm volatile("ldmatrix.sync.aligned.m8n8.x4.trans.shared.b16 {%0,%1,%2,%3}, [%4];\n"
                 : "=r"(r0), "=r"(r1), "=r"(r2), "=r"(r3) : "r"(a));
}
__device__ __forceinline__ void mma16816(float* c, const unsigned* a, unsigned b0, unsigned b1) {
    asm volatile("mma.sync.aligned.m16n8k16.row.col.f32.f16.f16.f32 "
                 "{%0,%1,%2,%3}, {%4,%5,%6,%7}, {%8,%9}, {%0,%1,%2,%3};\n"
                 : "+f"(c[0]), "+f"(c[1]), "+f"(c[2]), "+f"(c[3])
                 : "r"(a[0]), "r"(a[1]), "r"(a[2]), "r"(a[3]), "r"(b0), "r"(b1));
}
__device__ __forceinline__ void mma16816z(float* c, const unsigned* a, unsigned b0, unsigned b1) {
    asm volatile("mma.sync.aligned.m16n8k16.row.col.f32.f16.f16.f32 "
                 "{%0,%1,%2,%3}, {%4,%5,%6,%7}, {%8,%9}, {%10,%11,%12,%13};\n"
                 : "=f"(c[0]), "=f"(c[1]), "=f"(c[2]), "=f"(c[3])
                 : "r"(a[0]), "r"(a[1]), "r"(a[2]), "r"(a[3]), "r"(b0), "r"(b1),
                   "f"(0.f), "f"(0.f), "f"(0.f), "f"(0.f));
}
// f16-accumulator QK MMA: D (f16x2 pair) = A*B, zero C.
__device__ __forceinline__ void mma16816zh(unsigned& c0, unsigned& c1,
                                           const unsigned* a, unsigned b0, unsigned b1) {
    asm volatile("mma.sync.aligned.m16n8k16.row.col.f16.f16.f16.f16 "
                 "{%0,%1}, {%2,%3,%4,%5}, {%6,%7}, {%8,%9};\n"
                 : "=r"(c0), "=r"(c1)
                 : "r"(a[0]), "r"(a[1]), "r"(a[2]), "r"(a[3]), "r"(b0), "r"(b1),
                   "r"(0u), "r"(0u));
}
__device__ __forceinline__ unsigned packh2(float x, float y) {
    __half2 h = __floats2half2_rn(x, y);
    return reinterpret_cast<unsigned&>(h);
}
__device__ __forceinline__ unsigned ex2h2(unsigned x) {
    unsigned r;
    asm volatile("ex2.approx.f16x2 %0, %1;\n" : "=r"(r) : "r"(x));
    return r;
}
__device__ __forceinline__ unsigned hadd2u(unsigned a, unsigned b) {
    __half2 r = __hadd2(reinterpret_cast<__half2&>(a), reinterpret_cast<__half2&>(b));
    return reinterpret_cast<unsigned&>(r);
}

// ---------------- fp16 conversion kernels ------------------------------------
__global__ __launch_bounds__(256) void conv_src_kernel(const float* __restrict__ in,
                                                       __half* __restrict__ out, int n) {
    int i = (blockIdx.x * 256 + threadIdx.x) * 4;
    if (i < n) {
        float4 v = *(const float4*)(in + i);
        *(__half2*)(out + i)     = __floats2half2_rn(v.x, v.y);
        *(__half2*)(out + i + 2) = __floats2half2_rn(v.z, v.w);
    }
}

__global__ __launch_bounds__(256) void conv_w_kernel(
    const float* wq, const float* wk, const float* wv, const float* wo,
    const float* w1, const float* w2,
    __half* oq, __half* ok, __half* ov, __half* oo, __half* o1, __half* o2)
{
    const float* in; __half* out; int n;
    switch (blockIdx.y) {
        case 0: in = wq; out = oq; n = DMODEL * DPROJ; break;
        case 1: in = wk; out = ok; n = DMODEL * DPROJ; break;
        case 2: in = wv; out = ov; n = DMODEL * DPROJ; break;
        case 3: in = wo; out = oo; n = DPROJ * DMODEL; break;
        case 4: in = w1; out = o1; n = DMODEL * DFF; break;
        default: in = w2; out = o2; n = DFF * DMODEL; break;
    }
    int i = (blockIdx.x * 256 + threadIdx.x) * 4;
    if (i < n) {
        float4 v = *(const float4*)(in + i);
        *(__half2*)(out + i)     = __floats2half2_rn(v.x, v.y);
        *(__half2*)(out + i + 2) = __floats2half2_rn(v.z, v.w);
    }
}

// ---------------- tensor-core GEMM (2-stage, static smem) --------------------
#define ASTR 40   // A smem row stride in halves

__device__ __forceinline__ void gemm_load_tile(
    unsigned aB, unsigned bB, const __half* __restrict__ A, const __half* __restrict__ B,
    int tid, int m0, int n0, int k0, int N, int K)
{
#pragma unroll
    for (int it = 0; it < 2; ++it) {
        int c = tid + it * 256;
        int row = c >> 2, ch = c & 3;
        cp16(aB + row * (ASTR * 2) + ch * 16,
             A + (size_t)(m0 + row) * K + k0 + ch * 8);
    }
#pragma unroll
    for (int it = 0; it < 2; ++it) {
        int c = tid + it * 256;
        int k = c >> 4, ch = c & 15;
        cp16(bB + k * 256 + ((ch ^ (k & 7)) << 4),
             B + (size_t)(k0 + k) * N + n0 + ch * 8);
    }
    cp_commit();
}

template <int OUT_HALF, int RELU>
__device__ __forceinline__ void gemm_body(
    const __half* __restrict__ A, const __half* __restrict__ B,
    const float* __restrict__ bias, void* __restrict__ Cout, int N, int K)
{
    __shared__ __half sA[2][128 * ASTR];
    __shared__ __half sB[2][32 * 128];

    const int tid = threadIdx.x;
    const int lane = tid & 31;
    const int wid = tid >> 5;
    const int wm = (wid >> 2) * 64;
    const int wn = (wid & 3) * 32;
    const int m0 = blockIdx.y * 128;
    const int n0 = blockIdx.x * 128;

    unsigned aB[2] = { smem_u32(sA[0]), smem_u32(sA[1]) };
    unsigned bB[2] = { smem_u32(sB[0]), smem_u32(sB[1]) };

    float acc[4][4][4] = {};

    const int KT = K >> 5;
    gemm_load_tile(aB[0], bB[0], A, B, tid, m0, n0, 0, N, K);

    const int lrow = lane & 15;
    const int lcol = (lane >> 4) * 8;

    for (int kt = 0; kt < KT; ++kt) {
        if (kt + 1 < KT) {
            gemm_load_tile(aB[(kt + 1) & 1], bB[(kt + 1) & 1], A, B, tid, m0, n0, (kt + 1) << 5, N, K);
            cp_wait1();
        } else {
            cp_wait0();
        }
        __syncthreads();
        const int buf = kt & 1;
#pragma unroll
        for (int s = 0; s < 2; ++s) {
            unsigned av[4][4];
#pragma unroll
            for (int i = 0; i < 4; ++i) {
                unsigned addr = aB[buf] + (unsigned)((wm + i * 16 + lrow) * (ASTR * 2) + (s * 16 + lcol) * 2);
                ldmx4(av[i][0], av[i][1], av[i][2], av[i][3], addr);
            }
#pragma unroll
            for (int p = 0; p < 2; ++p) {
                const int mi = lane >> 3, r = lane & 7;
                const int krow = s * 16 + (mi & 1) * 8 + r;
                const int nch = (wn >> 3) + p * 2 + (mi >> 1);
                unsigned addr = bB[buf] + (unsigned)(krow * 256 + ((nch ^ (krow & 7)) << 4));
                unsigned b0, b1, b2, b3;
                ldmx4t(b0, b1, b2, b3, addr);
#pragma unroll
                for (int i = 0; i < 4; ++i) {
                    mma16816(acc[i][2 * p + 0], av[i], b0, b1);
                    mma16816(acc[i][2 * p + 1], av[i], b2, b3);
                }
            }
        }
        __syncthreads();
    }

#pragma unroll
    for (int i = 0; i < 4; ++i) {
        const int row = m0 + wm + i * 16 + (lane >> 2);
#pragma unroll
        for (int j = 0; j < 4; ++j) {
            const int col = n0 + wn + j * 8 + (lane & 3) * 2;
            float c0 = acc[i][j][0], c1 = acc[i][j][1], c2 = acc[i][j][2], c3 = acc[i][j][3];
            if (bias) {
                float2 bv = *(const float2*)&bias[col];
                c0 += bv.x; c1 += bv.y; c2 += bv.x; c3 += bv.y;
            }
            if (RELU) {
                c0 = fmaxf(c0, 0.f); c1 = fmaxf(c1, 0.f);
                c2 = fmaxf(c2, 0.f); c3 = fmaxf(c3, 0.f);
            }
            if (OUT_HALF) {
                __half* Ch = (__half*)Cout;
                *(__half2*)&Ch[(size_t)row * N + col]       = __floats2half2_rn(c0, c1);
                *(__half2*)&Ch[(size_t)(row + 8) * N + col] = __floats2half2_rn(c2, c3);
            } else {
                float* Cf = (float*)Cout;
                *(float2*)&Cf[(size_t)row * N + col]       = make_float2(c0, c1);
                *(float2*)&Cf[(size_t)(row + 8) * N + col] = make_float2(c2, c3);
            }
        }
    }
}

template <int OUT_HALF, int RELU>
__global__ __launch_bounds__(256) void gemm_k(
    const __half* __restrict__ A, const __half* __restrict__ B,
    const float* __restrict__ bias, void* __restrict__ C, int N, int K)
{
    gemm_body<OUT_HALF, RELU>(A, B, bias, C, N, K);
}

__global__ __launch_bounds__(256) void qkv_gemm_k(
    const __half* __restrict__ A,
    const __half* __restrict__ Bq, const __half* __restrict__ Bk, const __half* __restrict__ Bv,
    const float* __restrict__ bq, const float* __restrict__ bk, const float* __restrict__ bv,
    __half* __restrict__ oq, __half* __restrict__ ok, __half* __restrict__ ov)
{
    const __half* B; const float* bias; __half* out;
    switch (blockIdx.z) {
        case 0:  B = Bq; bias = bq; out = oq; break;
        case 1:  B = Bk; bias = bk; out = ok; break;
        default: B = Bv; bias = bv; out = ov; break;
    }
    gemm_body<1, 0>(A, B, bias, out, DPROJ, DMODEL);
}

// ---------------- GEMM + residual + LayerNorm fused (N=256) ------------------
__device__ __forceinline__ void gemmln_load_tile(
    unsigned aB, unsigned bB, const __half* __restrict__ A, const __half* __restrict__ B,
    int tid, int m0, int k0, int K)
{
    {
        int row = tid >> 2, ch = tid & 3;
        cp16(aB + row * (ASTR * 2) + ch * 16,
             A + (size_t)(m0 + row) * K + k0 + ch * 8);
    }
#pragma unroll
    for (int it = 0; it < 4; ++it) {
        int c = tid + it * 256;
        int k = c >> 5, ch = c & 31;
        cp16(bB + k * 512 + ((ch ^ (k & 7)) << 4),
             B + (size_t)(k0 + k) * 256 + ch * 8);
    }
    cp_commit();
}

template <int HAS_BIAS, int OUT16>
__global__ __launch_bounds__(256) void gemm_ln_k(
    const __half* __restrict__ A, const __half* __restrict__ B,
    const float* __restrict__ bias, const float* __restrict__ res,
    const float* __restrict__ g, const float* __restrict__ be,
    float* __restrict__ out, __half* __restrict__ out16, int K)
{
    __shared__ __half sA[2][64 * ASTR];
    __shared__ __half sB[2][32 * 256];
    __shared__ float sS[64][2];
    __shared__ float sQ[64][2];
    __shared__ float sG[256];
    __shared__ float sBe[256];
    __shared__ float sBias[256];

    const int tid = threadIdx.x;
    const int lane = tid & 31;
    const int wid = tid >> 5;
    const int mwarp = wid >> 1;
    const int nwarp = wid & 1;
    const int moff = mwarp * 16;
    const int m0 = blockIdx.x * 64;

    sG[tid] = g[tid];
    sBe[tid] = be[tid];
    if (HAS_BIAS) sBias[tid] = bias[tid];

    unsigned aB[2] = { smem_u32(sA[0]), smem_u32(sA[1]) };
    unsigned bB[2] = { smem_u32(sB[0]), smem_u32(sB[1]) };

    float acc[16][4] = {};

    const int KT = K >> 5;
    gemmln_load_tile(aB[0], bB[0], A, B, tid, m0, 0, K);

    const int lrow = lane & 15;
    const int lcol = (lane >> 4) * 8;
    const int mi = lane >> 3, r = lane & 7;

    for (int kt = 0; kt < KT; ++kt) {
        if (kt + 1 < KT) {
            gemmln_load_tile(aB[(kt + 1) & 1], bB[(kt + 1) & 1], A, B, tid, m0, (kt + 1) << 5, K);
            cp_wait1();
        } else {
            cp_wait0();
        }
        __syncthreads();
        const int buf = kt & 1;
#pragma unroll
        for (int s = 0; s < 2; ++s) {
            unsigned av[4];
            {
                unsigned addr = aB[buf] + (unsigned)((moff + lrow) * (ASTR * 2) + (s * 16 + lcol) * 2);
                ldmx4(av[0], av[1], av[2], av[3], addr);
            }
            const int krow = s * 16 + (mi & 1) * 8 + r;
#pragma unroll
            for (int p = 0; p < 8; ++p) {
                const int nch = nwarp * 16 + p * 2 + (mi >> 1);
                unsigned addr = bB[buf] + (unsigned)(krow * 512 + ((nch ^ (krow & 7)) << 4));
                unsigned b0, b1, b2, b3;
                ldmx4t(b0, b1, b2, b3, addr);
                mma16816(acc[2 * p + 0], av, b0, b1);
                mma16816(acc[2 * p + 1], av, b2, b3);
            }
        }
        __syncthreads();
    }

    const int ra = m0 + moff + (lane >> 2);
    const int rb = ra + 8;
    const int cbase = nwarp * 128 + (lane & 3) * 2;

    float sumA = 0.f, sqA = 0.f, sumB = 0.f, sqB = 0.f;
#pragma unroll
    for (int j = 0; j < 16; ++j) {
        const int col = cbase + j * 8;
        float2 rA = *(const float2*)&res[(size_t)ra * 256 + col];
        float2 rB = *(const float2*)&res[(size_t)rb * 256 + col];
        float b0v = 0.f, b1v = 0.f;
        if (HAS_BIAS) { b0v = sBias[col]; b1v = sBias[col + 1]; }
        float v0 = acc[j][0] + b0v + rA.x;
        float v1 = acc[j][1] + b1v + rA.y;
        float v2 = acc[j][2] + b0v + rB.x;
        float v3 = acc[j][3] + b1v + rB.y;
        acc[j][0] = v0; acc[j][1] = v1; acc[j][2] = v2; acc[j][3] = v3;
        sumA += v0 + v1; sqA += v0 * v0 + v1 * v1;
        sumB += v2 + v3; sqB += v2 * v2 + v3 * v3;
    }
    sumA += __shfl_xor_sync(0xffffffffu, sumA, 1);
    sumA += __shfl_xor_sync(0xffffffffu, sumA, 2);
    sqA  += __shfl_xor_sync(0xffffffffu, sqA, 1);
    sqA  += __shfl_xor_sync(0xffffffffu, sqA, 2);
    sumB += __shfl_xor_sync(0xffffffffu, sumB, 1);
    sumB += __shfl_xor_sync(0xffffffffu, sumB, 2);
    sqB  += __shfl_xor_sync(0xffffffffu, sqB, 1);
    sqB  += __shfl_xor_sync(0xffffffffu, sqB, 2);
    if ((lane & 3) == 0) {
        const int rl = moff + (lane >> 2);
        sS[rl][nwarp] = sumA; sQ[rl][nwarp] = sqA;
        sS[rl + 8][nwarp] = sumB; sQ[rl + 8][nwarp] = sqB;
    }
    __syncthreads();

    const int rlA = moff + (lane >> 2);
    const float totSA = sS[rlA][0] + sS[rlA][1];
    const float totQA = sQ[rlA][0] + sQ[rlA][1];
    const float muA = totSA * (1.0f / 256.0f);
    const float rsA = rsqrtf(totQA * (1.0f / 256.0f) - muA * muA + 1e-5f);
    const float totSB = sS[rlA + 8][0] + sS[rlA + 8][1];
    const float totQB = sQ[rlA + 8][0] + sQ[rlA + 8][1];
    const float muB = totSB * (1.0f / 256.0f);
    const float rsB = rsqrtf(totQB * (1.0f / 256.0f) - muB * muB + 1e-5f);

#pragma unroll
    for (int j = 0; j < 16; ++j) {
        const int col = cbase + j * 8;
        const float g0 = sG[col], g1 = sG[col + 1];
        const float e0 = sBe[col], e1 = sBe[col + 1];
        float o0 = (acc[j][0] - muA) * rsA * g0 + e0;
        float o1 = (acc[j][1] - muA) * rsA * g1 + e1;
        float o2 = (acc[j][2] - muB) * rsB * g0 + e0;
        float o3 = (acc[j][3] - muB) * rsB * g1 + e1;
        *(float2*)&out[(size_t)ra * 256 + col] = make_float2(o0, o1);
        *(float2*)&out[(size_t)rb * 256 + col] = make_float2(o2, o3);
        if (OUT16) {
            *(__half2*)&out16[(size_t)ra * 256 + col] = __floats2half2_rn(o0, o1);
            *(__half2*)&out16[(size_t)rb * 256 + col] = __floats2half2_rn(o2, o3);
        }
    }
}

// ---------------- flash attention: 32 queries/warp, phase-rotated warps ------
// r12 body + warp phase rotation: odd warps start the 8-step loop at step 4,
// so at any instant half the warps are in the MUFU (ex2) phase while the other
// half are in the tensor (HMMA) phase -> the two per-SMSP pipe floors overlap
// instead of serializing.
#define KSTR 24

__device__ __forceinline__ void attn_load_kv(
    unsigned kB, unsigned vB, const __half* __restrict__ k, const __half* __restrict__ v,
    int tid, int kstart, int b, int h)
{
    const int row = tid >> 1, ch = tid & 1;
    const size_t g = ((size_t)(kstart + row) * BATCH + b) * DPROJ + h * DH + ch * 8;
    cp16(kB + row * (KSTR * 2) + ch * 16, k + g);
    cp16(vB + row * (KSTR * 2) + ch * 16, v + g);
}

__global__ __launch_bounds__(256) void attn_kernel(
    const __half* __restrict__ q, const __half* __restrict__ k,
    const __half* __restrict__ v, __half* __restrict__ ctx)
{
    __shared__ __half sQ[256 * KSTR];
    __shared__ __half sK[2][128 * KSTR];
    __shared__ __half sV[2][128 * KSTR];

    const int tid = threadIdx.x;
    const int lane = tid & 31;
    const int wid = tid >> 5;
    const int qt = blockIdx.x;
    const int bh = blockIdx.y;
    const int b = bh >> 3, h = bh & 7;
    const int q0 = qt * 256;
    const int wq = wid * 32;
    const int soff = (wid & 1) << 2;   // phase rotation: odd warps start at step 4

    unsigned qB = smem_u32(sQ);
    unsigned kB[2] = { smem_u32(sK[0]), smem_u32(sK[1]) };
    unsigned vB[2] = { smem_u32(sV[0]), smem_u32(sV[1]) };

    const unsigned bones = (lane < 4) ? 0x3C003C00u : 0u;

    {
        const size_t g = ((size_t)(q0 + tid) * BATCH + b) * DPROJ + h * DH;
        cp16(qB + tid * (KSTR * 2), q + g);
        cp16(qB + tid * (KSTR * 2) + 16, q + g + 8);
    }
    attn_load_kv(kB[0], vB[0], k, v, tid, 0, b, h);
    cp_commit();

    float o00[4] = {}, o01[4] = {}, o10[4] = {}, o11[4] = {};
    float ol0[4] = {}, ol1[4] = {};
    unsigned qa0[4], qa1[4];

    const int mi = lane >> 3, r = lane & 7;
    const unsigned vrow_off = (unsigned)(((mi & 1) * 8 + r) * (KSTR * 2) + (mi >> 1) * 16);

    for (int kt = 0; kt < SEQ / 128; ++kt) {
        if (kt + 1 < SEQ / 128) {
            attn_load_kv(kB[(kt + 1) & 1], vB[(kt + 1) & 1], k, v, tid, (kt + 1) * 128, b, h);
            cp_commit();
            cp_wait1();
        } else {
            cp_wait0();
        }
        __syncthreads();
        const int buf = kt & 1;

        if (kt == 0) {
            const __half2 ce2 = __float2half2_rn(0.25f * 1.44269504088896f);
            unsigned base = qB + (unsigned)((wq + (lane >> 2)) * (KSTR * 2) + (lane & 3) * 4);
#pragma unroll
            for (int m = 0; m < 2; ++m) {
                unsigned* qa = m ? qa1 : qa0;
                unsigned bb = base + (unsigned)(m * 16 * (KSTR * 2));
                qa[0] = lds_u32(bb);
                qa[1] = lds_u32(bb + 8 * (KSTR * 2));
                qa[2] = lds_u32(bb + 16);
                qa[3] = lds_u32(bb + 8 * (KSTR * 2) + 16);
#pragma unroll
                for (int i = 0; i < 4; ++i) {
                    __half2 t = __hmul2(reinterpret_cast<__half2&>(qa[i]), ce2);
                    qa[i] = reinterpret_cast<unsigned&>(t);
                }
            }
        }

        const unsigned kfrag = kB[buf] + (unsigned)((lane >> 2) * (KSTR * 2) + (lane & 3) * 4);
        unsigned ps0[4] = {0u, 0u, 0u, 0u};
        unsigned ps1[4] = {0u, 0u, 0u, 0u};

#pragma unroll
        for (int ss = 0; ss < 8; ++ss) {
            const int s = (ss + soff) & 7;
            unsigned kb0 = kfrag + (unsigned)((s * 16) * (KSTR * 2));
            unsigned kb1 = kb0 + (unsigned)(8 * (KSTR * 2));
            unsigned k00 = lds_u32(kb0), k01 = lds_u32(kb0 + 16);
            unsigned k10 = lds_u32(kb1), k11 = lds_u32(kb1 + 16);

            // S in fp16 directly (log2 domain, |s| small) -> no F2FP
            unsigned sa0_0, sa0_1, sa1_0, sa1_1;   // m-tile 0
            unsigned sb0_0, sb0_1, sb1_0, sb1_1;   // m-tile 1
            mma16816zh(sa0_0, sa0_1, qa0, k00, k01);
            mma16816zh(sa1_0, sa1_1, qa0, k10, k11);
            mma16816zh(sb0_0, sb0_1, qa1, k00, k01);
            mma16816zh(sb1_0, sb1_1, qa1, k10, k11);

            unsigned pa[4], pb[4];
            pa[0] = ex2h2(sa0_0);
            pa[1] = ex2h2(sa0_1);
            pa[2] = ex2h2(sa1_0);
            pa[3] = ex2h2(sa1_1);
            pb[0] = ex2h2(sb0_0);
            pb[1] = ex2h2(sb0_1);
            pb[2] = ex2h2(sb1_0);
            pb[3] = ex2h2(sb1_1);

            ps0[0] = hadd2u(ps0[0], pa[0]); ps0[1] = hadd2u(ps0[1], pa[1]);
            ps0[2] = hadd2u(ps0[2], pa[2]); ps0[3] = hadd2u(ps0[3], pa[3]);
            ps1[0] = hadd2u(ps1[0], pb[0]); ps1[1] = hadd2u(ps1[1], pb[1]);
            ps1[2] = hadd2u(ps1[2], pb[2]); ps1[3] = hadd2u(ps1[3], pb[3]);

            unsigned addr = vB[buf] + (unsigned)(s * 16 * (KSTR * 2)) + vrow_off;
            unsigned vb0, vb1, vb2, vb3;
            ldmx4t(vb0, vb1, vb2, vb3, addr);
            mma16816(o00, pa, vb0, vb1);
            mma16816(o01, pa, vb2, vb3);
            mma16816(o10, pb, vb0, vb1);
            mma16816(o11, pb, vb2, vb3);
        }
        mma16816(ol0, ps0, bones, bones);
        mma16816(ol1, ps1, bones, bones);
        __syncthreads();
    }

    float l00 = __shfl_sync(0xffffffffu, ol0[0], lane & 28);
    float l01 = __shfl_sync(0xffffffffu, ol0[2], lane & 28);
    float l10 = __shfl_sync(0xffffffffu, ol1[0], lane & 28);
    float l11 = __shfl_sync(0xffffffffu, ol1[2], lane & 28);
    const float i00 = 1.f / l00, i01 = 1.f / l01;
    const float i10 = 1.f / l10, i11 = 1.f / l11;

    const int rbase = q0 + wq + (lane >> 2);
    const int col0 = h * DH + (lane & 3) * 2;
    const int col1 = col0 + 8;
    *(__half2*)&ctx[((size_t)rbase * BATCH + b) * DPROJ + col0] =
        __floats2half2_rn(o00[0] * i00, o00[1] * i00);
    *(__half2*)&ctx[((size_t)(rbase + 8) * BATCH + b) * DPROJ + col0] =
        __floats2half2_rn(o00[2] * i01, o00[3] * i01);
    *(__half2*)&ctx[((size_t)rbase * BATCH + b) * DPROJ + col1] =
        __floats2half2_rn(o01[0] * i00, o01[1] * i00);
    *(__half2*)&ctx[((size_t)(rbase + 8) * BATCH + b) * DPROJ + col1] =
        __floats2half2_rn(o01[2] * i01, o01[3] * i01);
    *(__half2*)&ctx[((size_t)(rbase + 16) * BATCH + b) * DPROJ + col0] =
        __floats2half2_rn(o10[0] * i10, o10[1] * i10);
    *(__half2*)&ctx[((size_t)(rbase + 24) * BATCH + b) * DPROJ + col0] =
        __floats2half2_rn(o10[2] * i11, o10[3] * i11);
    *(__half2*)&ctx[((size_t)(rbase + 16) * BATCH + b) * DPROJ + col1] =
        __floats2half2_rn(o11[0] * i10, o11[1] * i10);
    *(__half2*)&ctx[((size_t)(rbase + 24) * BATCH + b) * DPROJ + col1] =
        __floats2half2_rn(o11[2] * i11, o11[3] * i11);
}

// ---------------- launch ----------------------------------------------------
extern "C" void kernel_launch(void* const* d_in, const int* in_sizes, int n_in,
                              void* d_out, int out_size)
{
    const float* src   = (const float*)d_in[0];
    const float* Wq    = (const float*)d_in[1];
    const float* bq    = (const float*)d_in[2];
    const float* Wk    = (const float*)d_in[3];
    const float* bk    = (const float*)d_in[4];
    const float* Wv    = (const float*)d_in[5];
    const float* bv    = (const float*)d_in[6];
    const float* Wo    = (const float*)d_in[7];
    const float* ln1_g = (const float*)d_in[8];
    const float* ln1_b = (const float*)d_in[9];
    const float* W1    = (const float*)d_in[10];
    const float* b1    = (const float*)d_in[11];
    const float* W2    = (const float*)d_in[12];
    const float* b2    = (const float*)d_in[13];
    const float* ln2_g = (const float*)d_in[14];
    const float* ln2_b = (const float*)d_in[15];
    float* out = (float*)d_out;

    __half *p_q, *p_k, *p_v, *p_ctx, *p_h, *p_x16, *p_src16;
    __half *p_wq, *p_wk, *p_wv, *p_wo, *p_w1, *p_w2;
    float *p_x;
    cudaGetSymbolAddress((void**)&p_q, g_q16);
    cudaGetSymbolAddress((void**)&p_k, g_k16);
    cudaGetSymbolAddress((void**)&p_v, g_v16);
    cudaGetSymbolAddress((void**)&p_ctx, g_ctx16);
    cudaGetSymbolAddress((void**)&p_h, g_h16);
    cudaGetSymbolAddress((void**)&p_x16, g_x16);
    cudaGetSymbolAddress((void**)&p_src16, g_src16);
    cudaGetSymbolAddress((void**)&p_wq, g_wq16);
    cudaGetSymbolAddress((void**)&p_wk, g_wk16);
    cudaGetSymbolAddress((void**)&p_wv, g_wv16);
    cudaGetSymbolAddress((void**)&p_wo, g_wo16);
    cudaGetSymbolAddress((void**)&p_w1, g_w116);
    cudaGetSymbolAddress((void**)&p_w2, g_w216);
    cudaGetSymbolAddress((void**)&p_x, g_x);

    // 0. fp16 conversions
    conv_w_kernel<<<dim3(256, 6), 256>>>(Wq, Wk, Wv, Wo, W1, W2,
                                         p_wq, p_wk, p_wv, p_wo, p_w1, p_w2);
    conv_src_kernel<<<(MROWS * DMODEL) / 1024, 256>>>(src, p_src16, MROWS * DMODEL);

    // 1. QKV projections (fused, z selects matrix), fp16 out
    {
        dim3 grid(DPROJ / 128, MROWS / 128, 3);
        qkv_gemm_k<<<grid, 256>>>(p_src16, p_wq, p_wk, p_wv, bq, bk, bv, p_q, p_k, p_v);
    }
    // 2. attention -> ctx fp16 (256 queries per CTA)
    {
        dim3 grid(SEQ / 256, BATCH * NHEADS);
        attn_kernel<<<grid, 256>>>(p_q, p_k, p_v, p_ctx);
    }
    // 3+4. x = LN1(src + ctx@Wo), fused: writes x fp32 + x16 fp16
    gemm_ln_k<0, 1><<<MROWS / 64, 256>>>(p_ctx, p_wo, nullptr, src,
                                         ln1_g, ln1_b, p_x, p_x16, DPROJ);
    // 5. h = relu(x @ W1 + b1), fp16 out
    {
        dim3 grid(DFF / 128, MROWS / 128);
        gemm_k<1, 1><<<grid, 256>>>(p_x16, p_w1, b1, p_h, DFF, DMODEL);
    }
    // 6+7. out = LN2(x + h@W2 + b2), fused
    gemm_ln_k<1, 0><<<MROWS / 64, 256>>>(p_h, p_w2, b2, p_x,
                                         ln2_g, ln2_b, out, nullptr, DFF);
}

// round 15
// speedup vs baseline: 1.0401x; 1.0401x over previous
#include <cuda_runtime.h>
#include <cuda_fp16.h>
#include <cstddef>

#define SEQ 2048
#define BATCH 8
#define DMODEL 256
#define NHEADS 8
#define DPROJ 128
#define DFF 1024
#define DH 16
#define MROWS (SEQ*BATCH)   // 16384

// ---------------- scratch (device globals; no allocations allowed) -----------
__device__ __half g_q16[(size_t)MROWS * DPROJ];
__device__ __half g_k16[(size_t)MROWS * DPROJ];
__device__ __half g_v16[(size_t)MROWS * DPROJ];
__device__ __half g_ctx16[(size_t)MROWS * DPROJ];
__device__ __half g_h16[(size_t)MROWS * DFF];
__device__ __half g_x16[(size_t)MROWS * DMODEL];
__device__ __half g_src16[(size_t)MROWS * DMODEL];
__device__ float  g_x[(size_t)MROWS * DMODEL];
__device__ __half g_wq16[DMODEL * DPROJ];
__device__ __half g_wk16[DMODEL * DPROJ];
__device__ __half g_wv16[DMODEL * DPROJ];
__device__ __half g_wo16[DPROJ * DMODEL];
__device__ __half g_w116[DMODEL * DFF];
__device__ __half g_w216[DFF * DMODEL];

// ---------------- PTX helpers ------------------------------------------------
__device__ __forceinline__ unsigned smem_u32(const void* p) {
    return (unsigned)__cvta_generic_to_shared(p);
}
__device__ __forceinline__ void cp16(unsigned dst, const void* src) {
    asm volatile("cp.async.cg.shared.global [%0], [%1], 16;\n" :: "r"(dst), "l"(src));
}
__device__ __forceinline__ void cp_commit() {
    asm volatile("cp.async.commit_group;\n" ::);
}
__device__ __forceinline__ void cp_wait1() {
    asm volatile("cp.async.wait_group 1;\n" ::);
}
__device__ __forceinline__ void cp_wait0() {
    asm volatile("cp.async.wait_group 0;\n" ::);
}
__device__ __forceinline__ unsigned lds_u32(unsigned a) {
    unsigned v;
    asm volatile("ld.shared.u32 %0, [%1];\n" : "=r"(v) : "r"(a));
    return v;
}
__device__ __forceinline__ void ldmx4(unsigned& r0, unsigned& r1, unsigned& r2, unsigned& r3, unsigned a) {
    asm volatile("ldmatrix.sync.aligned.m8n8.x4.shared.b16 {%0,%1,%2,%3}, [%4];\n"
                 : "=r"(r0), "=r"(r1), "=r"(r2), "=r"(r3) : "r"(a));
}
__device__ __forceinline__ void ldmx4t(unsigned& r0, unsigned& r1, unsigned& r2, unsigned& r3, unsigned a) {
    asm volatile("ldmatrix.sync.aligned.m8n8.x4.trans.shared.b16 {%0,%1,%2,%3}, [%4];\n"
                 : "=r"(r0), "=r"(r1), "=r"(r2), "=r"(r3) : "r"(a));
}
__device__ __forceinline__ void mma16816(float* c, const unsigned* a, unsigned b0, unsigned b1) {
    asm volatile("mma.sync.aligned.m16n8k16.row.col.f32.f16.f16.f32 "
                 "{%0,%1,%2,%3}, {%4,%5,%6,%7}, {%8,%9}, {%0,%1,%2,%3};\n"
                 : "+f"(c[0]), "+f"(c[1]), "+f"(c[2]), "+f"(c[3])
                 : "r"(a[0]), "r"(a[1]), "r"(a[2]), "r"(a[3]), "r"(b0), "r"(b1));
}
__device__ __forceinline__ void mma16816z(float* c, const unsigned* a, unsigned b0, unsigned b1) {
    asm volatile("mma.sync.aligned.m16n8k16.row.col.f32.f16.f16.f32 "
                 "{%0,%1,%2,%3}, {%4,%5,%6,%7}, {%8,%9}, {%10,%11,%12,%13};\n"
                 : "=f"(c[0]), "=f"(c[1]), "=f"(c[2]), "=f"(c[3])
                 : "r"(a[0]), "r"(a[1]), "r"(a[2]), "r"(a[3]), "r"(b0), "r"(b1),
                   "f"(0.f), "f"(0.f), "f"(0.f), "f"(0.f));
}
// f16-accumulator QK MMA: D (f16x2 pair) = A*B, zero C.
__device__ __forceinline__ void mma16816zh(unsigned& c0, unsigned& c1,
                                           const unsigned* a, unsigned b0, unsigned b1) {
    asm volatile("mma.sync.aligned.m16n8k16.row.col.f16.f16.f16.f16 "
                 "{%0,%1}, {%2,%3,%4,%5}, {%6,%7}, {%8,%9};\n"
                 : "=r"(c0), "=r"(c1)
                 : "r"(a[0]), "r"(a[1]), "r"(a[2]), "r"(a[3]), "r"(b0), "r"(b1),
                   "r"(0u), "r"(0u));
}
__device__ __forceinline__ unsigned packh2(float x, float y) {
    __half2 h = __floats2half2_rn(x, y);
    return reinterpret_cast<unsigned&>(h);
}
__device__ __forceinline__ unsigned ex2h2(unsigned x) {
    unsigned r;
    asm volatile("ex2.approx.f16x2 %0, %1;\n" : "=r"(r) : "r"(x));
    return r;
}
__device__ __forceinline__ unsigned hadd2u(unsigned a, unsigned b) {
    __half2 r = __hadd2(reinterpret_cast<__half2&>(a), reinterpret_cast<__half2&>(b));
    return reinterpret_cast<unsigned&>(r);
}

// ---------------- fp16 conversion kernels ------------------------------------
__global__ __launch_bounds__(256) void conv_src_kernel(const float* __restrict__ in,
                                                       __half* __restrict__ out, int n) {
    int i = (blockIdx.x * 256 + threadIdx.x) * 4;
    if (i < n) {
        float4 v = *(const float4*)(in + i);
        *(__half2*)(out + i)     = __floats2half2_rn(v.x, v.y);
        *(__half2*)(out + i + 2) = __floats2half2_rn(v.z, v.w);
    }
}

__global__ __launch_bounds__(256) void conv_w_kernel(
    const float* wq, const float* wk, const float* wv, const float* wo,
    const float* w1, const float* w2,
    __half* oq, __half* ok, __half* ov, __half* oo, __half* o1, __half* o2)
{
    const float* in; __half* out; int n;
    switch (blockIdx.y) {
        case 0: in = wq; out = oq; n = DMODEL * DPROJ; break;
        case 1: in = wk; out = ok; n = DMODEL * DPROJ; break;
        case 2: in = wv; out = ov; n = DMODEL * DPROJ; break;
        case 3: in = wo; out = oo; n = DPROJ * DMODEL; break;
        case 4: in = w1; out = o1; n = DMODEL * DFF; break;
        default: in = w2; out = o2; n = DFF * DMODEL; break;
    }
    int i = (blockIdx.x * 256 + threadIdx.x) * 4;
    if (i < n) {
        float4 v = *(const float4*)(in + i);
        *(__half2*)(out + i)     = __floats2half2_rn(v.x, v.y);
        *(__half2*)(out + i + 2) = __floats2half2_rn(v.z, v.w);
    }
}

// ---------------- tensor-core GEMM (2-stage, static smem, BM templated) ------
// C[M,N] = A[M,K] @ B[K,N] (+bias, relu). BM in {64,128}, BN=128, BK=32,
// 256 threads. BM=64 halves per-CTA work -> finer wave granularity for
// small-grid GEMMs (QKV), cutting tail-wave idle time.
#define ASTR 40   // A smem row stride in halves

template <int BM>
__device__ __forceinline__ void gemm_load_tile(
    unsigned aB, unsigned bB, const __half* __restrict__ A, const __half* __restrict__ B,
    int tid, int m0, int n0, int k0, int N, int K)
{
#pragma unroll
    for (int it = 0; it < BM / 64; ++it) {
        int c = tid + it * 256;
        int row = c >> 2, ch = c & 3;
        cp16(aB + row * (ASTR * 2) + ch * 16,
             A + (size_t)(m0 + row) * K + k0 + ch * 8);
    }
#pragma unroll
    for (int it = 0; it < 2; ++it) {
        int c = tid + it * 256;
        int k = c >> 4, ch = c & 15;
        cp16(bB + k * 256 + ((ch ^ (k & 7)) << 4),
             B + (size_t)(k0 + k) * N + n0 + ch * 8);
    }
    cp_commit();
}

template <int BM, int OUT_HALF, int RELU>
__device__ __forceinline__ void gemm_body(
    const __half* __restrict__ A, const __half* __restrict__ B,
    const float* __restrict__ bias, void* __restrict__ Cout, int N, int K)
{
    constexpr int MI = BM / 32;   // 16-row frags per warp: BM=128 -> 4, BM=64 -> 2
    __shared__ __half sA[2][BM * ASTR];
    __shared__ __half sB[2][32 * 128];

    const int tid = threadIdx.x;
    const int lane = tid & 31;
    const int wid = tid >> 5;
    const int wm = (wid >> 2) * (BM / 2);
    const int wn = (wid & 3) * 32;
    const int m0 = blockIdx.y * BM;
    const int n0 = blockIdx.x * 128;

    unsigned aB[2] = { smem_u32(sA[0]), smem_u32(sA[1]) };
    unsigned bB[2] = { smem_u32(sB[0]), smem_u32(sB[1]) };

    float acc[MI][4][4] = {};

    const int KT = K >> 5;
    gemm_load_tile<BM>(aB[0], bB[0], A, B, tid, m0, n0, 0, N, K);

    const int lrow = lane & 15;
    const int lcol = (lane >> 4) * 8;

    for (int kt = 0; kt < KT; ++kt) {
        if (kt + 1 < KT) {
            gemm_load_tile<BM>(aB[(kt + 1) & 1], bB[(kt + 1) & 1], A, B, tid, m0, n0, (kt + 1) << 5, N, K);
            cp_wait1();
        } else {
            cp_wait0();
        }
        __syncthreads();
        const int buf = kt & 1;
#pragma unroll
        for (int s = 0; s < 2; ++s) {
            unsigned av[MI][4];
#pragma unroll
            for (int i = 0; i < MI; ++i) {
                unsigned addr = aB[buf] + (unsigned)((wm + i * 16 + lrow) * (ASTR * 2) + (s * 16 + lcol) * 2);
                ldmx4(av[i][0], av[i][1], av[i][2], av[i][3], addr);
            }
#pragma unroll
            for (int p = 0; p < 2; ++p) {
                const int mi = lane >> 3, r = lane & 7;
                const int krow = s * 16 + (mi & 1) * 8 + r;
                const int nch = (wn >> 3) + p * 2 + (mi >> 1);
                unsigned addr = bB[buf] + (unsigned)(krow * 256 + ((nch ^ (krow & 7)) << 4));
                unsigned b0, b1, b2, b3;
                ldmx4t(b0, b1, b2, b3, addr);
#pragma unroll
                for (int i = 0; i < MI; ++i) {
                    mma16816(acc[i][2 * p + 0], av[i], b0, b1);
                    mma16816(acc[i][2 * p + 1], av[i], b2, b3);
                }
            }
        }
        __syncthreads();
    }

#pragma unroll
    for (int i = 0; i < MI; ++i) {
        const int row = m0 + wm + i * 16 + (lane >> 2);
#pragma unroll
        for (int j = 0; j < 4; ++j) {
            const int col = n0 + wn + j * 8 + (lane & 3) * 2;
            float c0 = acc[i][j][0], c1 = acc[i][j][1], c2 = acc[i][j][2], c3 = acc[i][j][3];
            if (bias) {
                float2 bv = *(const float2*)&bias[col];
                c0 += bv.x; c1 += bv.y; c2 += bv.x; c3 += bv.y;
            }
            if (RELU) {
                c0 = fmaxf(c0, 0.f); c1 = fmaxf(c1, 0.f);
                c2 = fmaxf(c2, 0.f); c3 = fmaxf(c3, 0.f);
            }
            if (OUT_HALF) {
                __half* Ch = (__half*)Cout;
                *(__half2*)&Ch[(size_t)row * N + col]       = __floats2half2_rn(c0, c1);
                *(__half2*)&Ch[(size_t)(row + 8) * N + col] = __floats2half2_rn(c2, c3);
            } else {
                float* Cf = (float*)Cout;
                *(float2*)&Cf[(size_t)row * N + col]       = make_float2(c0, c1);
                *(float2*)&Cf[(size_t)(row + 8) * N + col] = make_float2(c2, c3);
            }
        }
    }
}

template <int OUT_HALF, int RELU>
__global__ __launch_bounds__(256) void gemm_k(
    const __half* __restrict__ A, const __half* __restrict__ B,
    const float* __restrict__ bias, void* __restrict__ C, int N, int K)
{
    gemm_body<128, OUT_HALF, RELU>(A, B, bias, C, N, K);
}

__global__ __launch_bounds__(256) void qkv_gemm_k(
    const __half* __restrict__ A,
    const __half* __restrict__ Bq, const __half* __restrict__ Bk, const __half* __restrict__ Bv,
    const float* __restrict__ bq, const float* __restrict__ bk, const float* __restrict__ bv,
    __half* __restrict__ oq, __half* __restrict__ ok, __half* __restrict__ ov)
{
    const __half* B; const float* bias; __half* out;
    switch (blockIdx.z) {
        case 0:  B = Bq; bias = bq; out = oq; break;
        case 1:  B = Bk; bias = bk; out = ok; break;
        default: B = Bv; bias = bv; out = ov; break;
    }
    gemm_body<64, 1, 0>(A, B, bias, out, DPROJ, DMODEL);
}

// ---------------- GEMM + residual + LayerNorm fused (N=256) ------------------
__device__ __forceinline__ void gemmln_load_tile(
    unsigned aB, unsigned bB, const __half* __restrict__ A, const __half* __restrict__ B,
    int tid, int m0, int k0, int K)
{
    {
        int row = tid >> 2, ch = tid & 3;
        cp16(aB + row * (ASTR * 2) + ch * 16,
             A + (size_t)(m0 + row) * K + k0 + ch * 8);
    }
#pragma unroll
    for (int it = 0; it < 4; ++it) {
        int c = tid + it * 256;
        int k = c >> 5, ch = c & 31;
        cp16(bB + k * 512 + ((ch ^ (k & 7)) << 4),
             B + (size_t)(k0 + k) * 256 + ch * 8);
    }
    cp_commit();
}

template <int HAS_BIAS, int OUT16>
__global__ __launch_bounds__(256) void gemm_ln_k(
    const __half* __restrict__ A, const __half* __restrict__ B,
    const float* __restrict__ bias, const float* __restrict__ res,
    const float* __restrict__ g, const float* __restrict__ be,
    float* __restrict__ out, __half* __restrict__ out16, int K)
{
    __shared__ __half sA[2][64 * ASTR];
    __shared__ __half sB[2][32 * 256];
    __shared__ float sS[64][2];
    __shared__ float sQ[64][2];
    __shared__ float sG[256];
    __shared__ float sBe[256];
    __shared__ float sBias[256];

    const int tid = threadIdx.x;
    const int lane = tid & 31;
    const int wid = tid >> 5;
    const int mwarp = wid >> 1;
    const int nwarp = wid & 1;
    const int moff = mwarp * 16;
    const int m0 = blockIdx.x * 64;

    sG[tid] = g[tid];
    sBe[tid] = be[tid];
    if (HAS_BIAS) sBias[tid] = bias[tid];

    unsigned aB[2] = { smem_u32(sA[0]), smem_u32(sA[1]) };
    unsigned bB[2] = { smem_u32(sB[0]), smem_u32(sB[1]) };

    float acc[16][4] = {};

    const int KT = K >> 5;
    gemmln_load_tile(aB[0], bB[0], A, B, tid, m0, 0, K);

    const int lrow = lane & 15;
    const int lcol = (lane >> 4) * 8;
    const int mi = lane >> 3, r = lane & 7;

    for (int kt = 0; kt < KT; ++kt) {
        if (kt + 1 < KT) {
            gemmln_load_tile(aB[(kt + 1) & 1], bB[(kt + 1) & 1], A, B, tid, m0, (kt + 1) << 5, K);
            cp_wait1();
        } else {
            cp_wait0();
        }
        __syncthreads();
        const int buf = kt & 1;
#pragma unroll
        for (int s = 0; s < 2; ++s) {
            unsigned av[4];
            {
                unsigned addr = aB[buf] + (unsigned)((moff + lrow) * (ASTR * 2) + (s * 16 + lcol) * 2);
                ldmx4(av[0], av[1], av[2], av[3], addr);
            }
            const int krow = s * 16 + (mi & 1) * 8 + r;
#pragma unroll
            for (int p = 0; p < 8; ++p) {
                const int nch = nwarp * 16 + p * 2 + (mi >> 1);
                unsigned addr = bB[buf] + (unsigned)(krow * 512 + ((nch ^ (krow & 7)) << 4));
                unsigned b0, b1, b2, b3;
                ldmx4t(b0, b1, b2, b3, addr);
                mma16816(acc[2 * p + 0], av, b0, b1);
                mma16816(acc[2 * p + 1], av, b2, b3);
            }
        }
        __syncthreads();
    }

    const int ra = m0 + moff + (lane >> 2);
    const int rb = ra + 8;
    const int cbase = nwarp * 128 + (lane & 3) * 2;

    float sumA = 0.f, sqA = 0.f, sumB = 0.f, sqB = 0.f;
#pragma unroll
    for (int j = 0; j < 16; ++j) {
        const int col = cbase + j * 8;
        float2 rA = *(const float2*)&res[(size_t)ra * 256 + col];
        float2 rB = *(const float2*)&res[(size_t)rb * 256 + col];
        float b0v = 0.f, b1v = 0.f;
        if (HAS_BIAS) { b0v = sBias[col]; b1v = sBias[col + 1]; }
        float v0 = acc[j][0] + b0v + rA.x;
        float v1 = acc[j][1] + b1v + rA.y;
        float v2 = acc[j][2] + b0v + rB.x;
        float v3 = acc[j][3] + b1v + rB.y;
        acc[j][0] = v0; acc[j][1] = v1; acc[j][2] = v2; acc[j][3] = v3;
        sumA += v0 + v1; sqA += v0 * v0 + v1 * v1;
        sumB += v2 + v3; sqB += v2 * v2 + v3 * v3;
    }
    sumA += __shfl_xor_sync(0xffffffffu, sumA, 1);
    sumA += __shfl_xor_sync(0xffffffffu, sumA, 2);
    sqA  += __shfl_xor_sync(0xffffffffu, sqA, 1);
    sqA  += __shfl_xor_sync(0xffffffffu, sqA, 2);
    sumB += __shfl_xor_sync(0xffffffffu, sumB, 1);
    sumB += __shfl_xor_sync(0xffffffffu, sumB, 2);
    sqB  += __shfl_xor_sync(0xffffffffu, sqB, 1);
    sqB  += __shfl_xor_sync(0xffffffffu, sqB, 2);
    if ((lane & 3) == 0) {
        const int rl = moff + (lane >> 2);
        sS[rl][nwarp] = sumA; sQ[rl][nwarp] = sqA;
        sS[rl + 8][nwarp] = sumB; sQ[rl + 8][nwarp] = sqB;
    }
    __syncthreads();

    const int rlA = moff + (lane >> 2);
    const float totSA = sS[rlA][0] + sS[rlA][1];
    const float totQA = sQ[rlA][0] + sQ[rlA][1];
    const float muA = totSA * (1.0f / 256.0f);
    const float rsA = rsqrtf(totQA * (1.0f / 256.0f) - muA * muA + 1e-5f);
    const float totSB = sS[rlA + 8][0] + sS[rlA + 8][1];
    const float totQB = sQ[rlA + 8][0] + sQ[rlA + 8][1];
    const float muB = totSB * (1.0f / 256.0f);
    const float rsB = rsqrtf(totQB * (1.0f / 256.0f) - muB * muB + 1e-5f);

#pragma unroll
    for (int j = 0; j < 16; ++j) {
        const int col = cbase + j * 8;
        const float g0 = sG[col], g1 = sG[col + 1];
        const float e0 = sBe[col], e1 = sBe[col + 1];
        float o0 = (acc[j][0] - muA) * rsA * g0 + e0;
        float o1 = (acc[j][1] - muA) * rsA * g1 + e1;
        float o2 = (acc[j][2] - muB) * rsB * g0 + e0;
        float o3 = (acc[j][3] - muB) * rsB * g1 + e1;
        *(float2*)&out[(size_t)ra * 256 + col] = make_float2(o0, o1);
        *(float2*)&out[(size_t)rb * 256 + col] = make_float2(o2, o3);
        if (OUT16) {
            *(__half2*)&out16[(size_t)ra * 256 + col] = __floats2half2_rn(o0, o1);
            *(__half2*)&out16[(size_t)rb * 256 + col] = __floats2half2_rn(o2, o3);
        }
    }
}

// ---------------- flash attention: 32 queries/warp (r12 proven body) ---------
#define KSTR 24

__device__ __forceinline__ void attn_load_kv(
    unsigned kB, unsigned vB, const __half* __restrict__ k, const __half* __restrict__ v,
    int tid, int kstart, int b, int h)
{
    const int row = tid >> 1, ch = tid & 1;
    const size_t g = ((size_t)(kstart + row) * BATCH + b) * DPROJ + h * DH + ch * 8;
    cp16(kB + row * (KSTR * 2) + ch * 16, k + g);
    cp16(vB + row * (KSTR * 2) + ch * 16, v + g);
}

__global__ __launch_bounds__(256) void attn_kernel(
    const __half* __restrict__ q, const __half* __restrict__ k,
    const __half* __restrict__ v, __half* __restrict__ ctx)
{
    __shared__ __half sQ[256 * KSTR];
    __shared__ __half sK[2][128 * KSTR];
    __shared__ __half sV[2][128 * KSTR];

    const int tid = threadIdx.x;
    const int lane = tid & 31;
    const int wid = tid >> 5;
    const int qt = blockIdx.x;
    const int bh = blockIdx.y;
    const int b = bh >> 3, h = bh & 7;
    const int q0 = qt * 256;
    const int wq = wid * 32;

    unsigned qB = smem_u32(sQ);
    unsigned kB[2] = { smem_u32(sK[0]), smem_u32(sK[1]) };
    unsigned vB[2] = { smem_u32(sV[0]), smem_u32(sV[1]) };

    const unsigned bones = (lane < 4) ? 0x3C003C00u : 0u;

    {
        const size_t g = ((size_t)(q0 + tid) * BATCH + b) * DPROJ + h * DH;
        cp16(qB + tid * (KSTR * 2), q + g);
        cp16(qB + tid * (KSTR * 2) + 16, q + g + 8);
    }
    attn_load_kv(kB[0], vB[0], k, v, tid, 0, b, h);
    cp_commit();

    float o00[4] = {}, o01[4] = {}, o10[4] = {}, o11[4] = {};
    float ol0[4] = {}, ol1[4] = {};
    unsigned qa0[4], qa1[4];

    const int mi = lane >> 3, r = lane & 7;
    const unsigned vrow_off = (unsigned)(((mi & 1) * 8 + r) * (KSTR * 2) + (mi >> 1) * 16);

    for (int kt = 0; kt < SEQ / 128; ++kt) {
        if (kt + 1 < SEQ / 128) {
            attn_load_kv(kB[(kt + 1) & 1], vB[(kt + 1) & 1], k, v, tid, (kt + 1) * 128, b, h);
            cp_commit();
            cp_wait1();
        } else {
            cp_wait0();
        }
        __syncthreads();
        const int buf = kt & 1;

        if (kt == 0) {
            const __half2 ce2 = __float2half2_rn(0.25f * 1.44269504088896f);
            unsigned base = qB + (unsigned)((wq + (lane >> 2)) * (KSTR * 2) + (lane & 3) * 4);
#pragma unroll
            for (int m = 0; m < 2; ++m) {
                unsigned* qa = m ? qa1 : qa0;
                unsigned bb = base + (unsigned)(m * 16 * (KSTR * 2));
                qa[0] = lds_u32(bb);
                qa[1] = lds_u32(bb + 8 * (KSTR * 2));
                qa[2] = lds_u32(bb + 16);
                qa[3] = lds_u32(bb + 8 * (KSTR * 2) + 16);
#pragma unroll
                for (int i = 0; i < 4; ++i) {
                    __half2 t = __hmul2(reinterpret_cast<__half2&>(qa[i]), ce2);
                    qa[i] = reinterpret_cast<unsigned&>(t);
                }
            }
        }

        const unsigned kfrag = kB[buf] + (unsigned)((lane >> 2) * (KSTR * 2) + (lane & 3) * 4);
        unsigned ps0[4] = {0u, 0u, 0u, 0u};
        unsigned ps1[4] = {0u, 0u, 0u, 0u};

#pragma unroll
        for (int s = 0; s < 8; ++s) {
            unsigned kb0 = kfrag + (unsigned)((s * 16) * (KSTR * 2));
            unsigned kb1 = kb0 + (unsigned)(8 * (KSTR * 2));
            unsigned k00 = lds_u32(kb0), k01 = lds_u32(kb0 + 16);
            unsigned k10 = lds_u32(kb1), k11 = lds_u32(kb1 + 16);

            // S in fp16 directly (log2 domain, |s| small) -> no F2FP
            unsigned sa0_0, sa0_1, sa1_0, sa1_1;   // m-tile 0
            unsigned sb0_0, sb0_1, sb1_0, sb1_1;   // m-tile 1
            mma16816zh(sa0_0, sa0_1, qa0, k00, k01);
            mma16816zh(sa1_0, sa1_1, qa0, k10, k11);
            mma16816zh(sb0_0, sb0_1, qa1, k00, k01);
            mma16816zh(sb1_0, sb1_1, qa1, k10, k11);

            unsigned pa[4], pb[4];
            pa[0] = ex2h2(sa0_0);
            pa[1] = ex2h2(sa0_1);
            pa[2] = ex2h2(sa1_0);
            pa[3] = ex2h2(sa1_1);
            pb[0] = ex2h2(sb0_0);
            pb[1] = ex2h2(sb0_1);
            pb[2] = ex2h2(sb1_0);
            pb[3] = ex2h2(sb1_1);

            ps0[0] = hadd2u(ps0[0], pa[0]); ps0[1] = hadd2u(ps0[1], pa[1]);
            ps0[2] = hadd2u(ps0[2], pa[2]); ps0[3] = hadd2u(ps0[3], pa[3]);
            ps1[0] = hadd2u(ps1[0], pb[0]); ps1[1] = hadd2u(ps1[1], pb[1]);
            ps1[2] = hadd2u(ps1[2], pb[2]); ps1[3] = hadd2u(ps1[3], pb[3]);

            unsigned addr = vB[buf] + (unsigned)(s * 16 * (KSTR * 2)) + vrow_off;
            unsigned vb0, vb1, vb2, vb3;
            ldmx4t(vb0, vb1, vb2, vb3, addr);
            mma16816(o00, pa, vb0, vb1);
            mma16816(o01, pa, vb2, vb3);
            mma16816(o10, pb, vb0, vb1);
            mma16816(o11, pb, vb2, vb3);
        }
        mma16816(ol0, ps0, bones, bones);
        mma16816(ol1, ps1, bones, bones);
        __syncthreads();
    }

    float l00 = __shfl_sync(0xffffffffu, ol0[0], lane & 28);
    float l01 = __shfl_sync(0xffffffffu, ol0[2], lane & 28);
    float l10 = __shfl_sync(0xffffffffu, ol1[0], lane & 28);
    float l11 = __shfl_sync(0xffffffffu, ol1[2], lane & 28);
    const float i00 = 1.f / l00, i01 = 1.f / l01;
    const float i10 = 1.f / l10, i11 = 1.f / l11;

    const int rbase = q0 + wq + (lane >> 2);
    const int col0 = h * DH + (lane & 3) * 2;
    const int col1 = col0 + 8;
    *(__half2*)&ctx[((size_t)rbase * BATCH + b) * DPROJ + col0] =
        __floats2half2_rn(o00[0] * i00, o00[1] * i00);
    *(__half2*)&ctx[((size_t)(rbase + 8) * BATCH + b) * DPROJ + col0] =
        __floats2half2_rn(o00[2] * i01, o00[3] * i01);
    *(__half2*)&ctx[((size_t)rbase * BATCH + b) * DPROJ + col1] =
        __floats2half2_rn(o01[0] * i00, o01[1] * i00);
    *(__half2*)&ctx[((size_t)(rbase + 8) * BATCH + b) * DPROJ + col1] =
        __floats2half2_rn(o01[2] * i01, o01[3] * i01);
    *(__half2*)&ctx[((size_t)(rbase + 16) * BATCH + b) * DPROJ + col0] =
        __floats2half2_rn(o10[0] * i10, o10[1] * i10);
    *(__half2*)&ctx[((size_t)(rbase + 24) * BATCH + b) * DPROJ + col0] =
        __floats2half2_rn(o10[2] * i11, o10[3] * i11);
    *(__half2*)&ctx[((size_t)(rbase + 16) * BATCH + b) * DPROJ + col1] =
        __floats2half2_rn(o11[0] * i10, o11[1] * i10);
    *(__half2*)&ctx[((size_t)(rbase + 24) * BATCH + b) * DPROJ + col1] =
        __floats2half2_rn(o11[2] * i11, o11[3] * i11);
}

// ---------------- launch ----------------------------------------------------
extern "C" void kernel_launch(void* const* d_in, const int* in_sizes, int n_in,
                              void* d_out, int out_size)
{
    const float* src   = (const float*)d_in[0];
    const float* Wq    = (const float*)d_in[1];
    const float* bq    = (const float*)d_in[2];
    const float* Wk    = (const float*)d_in[3];
    const float* bk    = (const float*)d_in[4];
    const float* Wv    = (const float*)d_in[5];
    const float* bv    = (const float*)d_in[6];
    const float* Wo    = (const float*)d_in[7];
    const float* ln1_g = (const float*)d_in[8];
    const float* ln1_b = (const float*)d_in[9];
    const float* W1    = (const float*)d_in[10];
    const float* b1    = (const float*)d_in[11];
    const float* W2    = (const float*)d_in[12];
    const float* b2    = (const float*)d_in[13];
    const float* ln2_g = (const float*)d_in[14];
    const float* ln2_b = (const float*)d_in[15];
    float* out = (float*)d_out;

    __half *p_q, *p_k, *p_v, *p_ctx, *p_h, *p_x16, *p_src16;
    __half *p_wq, *p_wk, *p_wv, *p_wo, *p_w1, *p_w2;
    float *p_x;
    cudaGetSymbolAddress((void**)&p_q, g_q16);
    cudaGetSymbolAddress((void**)&p_k, g_k16);
    cudaGetSymbolAddress((void**)&p_v, g_v16);
    cudaGetSymbolAddress((void**)&p_ctx, g_ctx16);
    cudaGetSymbolAddress((void**)&p_h, g_h16);
    cudaGetSymbolAddress((void**)&p_x16, g_x16);
    cudaGetSymbolAddress((void**)&p_src16, g_src16);
    cudaGetSymbolAddress((void**)&p_wq, g_wq16);
    cudaGetSymbolAddress((void**)&p_wk, g_wk16);
    cudaGetSymbolAddress((void**)&p_wv, g_wv16);
    cudaGetSymbolAddress((void**)&p_wo, g_wo16);
    cudaGetSymbolAddress((void**)&p_w1, g_w116);
    cudaGetSymbolAddress((void**)&p_w2, g_w216);
    cudaGetSymbolAddress((void**)&p_x, g_x);

    // 0. fp16 conversions
    conv_w_kernel<<<dim3(256, 6), 256>>>(Wq, Wk, Wv, Wo, W1, W2,
                                         p_wq, p_wk, p_wv, p_wo, p_w1, p_w2);
    conv_src_kernel<<<(MROWS * DMODEL) / 1024, 256>>>(src, p_src16, MROWS * DMODEL);

    // 1. QKV projections: BM=64 tiles (768 CTAs) to cut the tail-wave idle
    {
        dim3 grid(DPROJ / 128, MROWS / 64, 3);
        qkv_gemm_k<<<grid, 256>>>(p_src16, p_wq, p_wk, p_wv, bq, bk, bv, p_q, p_k, p_v);
    }
    // 2. attention -> ctx fp16 (256 queries per CTA)
    {
        dim3 grid(SEQ / 256, BATCH * NHEADS);
        attn_kernel<<<grid, 256>>>(p_q, p_k, p_v, p_ctx);
    }
    // 3+4. x = LN1(src + ctx@Wo), fused: writes x fp32 + x16 fp16
    gemm_ln_k<0, 1><<<MROWS / 64, 256>>>(p_ctx, p_wo, nullptr, src,
                                         ln1_g, ln1_b, p_x, p_x16, DPROJ);
    // 5. h = relu(x @ W1 + b1), fp16 out
    {
        dim3 grid(DFF / 128, MROWS / 128);
        gemm_k<1, 1><<<grid, 256>>>(p_x16, p_w1, b1, p_h, DFF, DMODEL);
    }
    // 6+7. out = LN2(x + h@W2 + b2), fused
    gemm_ln_k<1, 0><<<MROWS / 64, 256>>>(p_h, p_w2, b2, p_x,
                                         ln2_g, ln2_b, out, nullptr, DFF);
}

// round 16
// speedup vs baseline: 1.0526x; 1.0120x over previous
#include <cuda_runtime.h>
#include <cuda_fp16.h>
#include <cstddef>

#define SEQ 2048
#define BATCH 8
#define DMODEL 256
#define NHEADS 8
#define DPROJ 128
#define DFF 1024
#define DH 16
#define MROWS (SEQ*BATCH)   // 16384

// ---------------- scratch (device globals; no allocations allowed) -----------
__device__ __half g_q16[(size_t)MROWS * DPROJ];
__device__ __half g_k16[(size_t)MROWS * DPROJ];
__device__ __half g_v16[(size_t)MROWS * DPROJ];
__device__ __half g_ctx16[(size_t)MROWS * DPROJ];
__device__ __half g_h16[(size_t)MROWS * DFF];
__device__ __half g_x16[(size_t)MROWS * DMODEL];
__device__ __half g_src16[(size_t)MROWS * DMODEL];
__device__ __half g_wq16[DMODEL * DPROJ];
__device__ __half g_wk16[DMODEL * DPROJ];
__device__ __half g_wv16[DMODEL * DPROJ];
__device__ __half g_wo16[DPROJ * DMODEL];
__device__ __half g_w116[DMODEL * DFF];
__device__ __half g_w216[DFF * DMODEL];

// ---------------- PTX helpers ------------------------------------------------
__device__ __forceinline__ unsigned smem_u32(const void* p) {
    return (unsigned)__cvta_generic_to_shared(p);
}
__device__ __forceinline__ void cp16(unsigned dst, const void* src) {
    asm volatile("cp.async.cg.shared.global [%0], [%1], 16;\n" :: "r"(dst), "l"(src));
}
__device__ __forceinline__ void cp_commit() {
    asm volatile("cp.async.commit_group;\n" ::);
}
__device__ __forceinline__ void cp_wait1() {
    asm volatile("cp.async.wait_group 1;\n" ::);
}
__device__ __forceinline__ void cp_wait0() {
    asm volatile("cp.async.wait_group 0;\n" ::);
}
__device__ __forceinline__ unsigned lds_u32(unsigned a) {
    unsigned v;
    asm volatile("ld.shared.u32 %0, [%1];\n" : "=r"(v) : "r"(a));
    return v;
}
__device__ __forceinline__ void ldmx4(unsigned& r0, unsigned& r1, unsigned& r2, unsigned& r3, unsigned a) {
    asm volatile("ldmatrix.sync.aligned.m8n8.x4.shared.b16 {%0,%1,%2,%3}, [%4];\n"
                 : "=r"(r0), "=r"(r1), "=r"(r2), "=r"(r3) : "r"(a));
}
__device__ __forceinline__ void ldmx4t(unsigned& r0, unsigned& r1, unsigned& r2, unsigned& r3, unsigned a) {
    asm volatile("ldmatrix.sync.aligned.m8n8.x4.trans.shared.b16 {%0,%1,%2,%3}, [%4];\n"
                 : "=r"(r0), "=r"(r1), "=r"(r2), "=r"(r3) : "r"(a));
}
__device__ __forceinline__ void mma16816(float* c, const unsigned* a, unsigned b0, unsigned b1) {
    asm volatile("mma.sync.aligned.m16n8k16.row.col.f32.f16.f16.f32 "
                 "{%0,%1,%2,%3}, {%4,%5,%6,%7}, {%8,%9}, {%0,%1,%2,%3};\n"
                 : "+f"(c[0]), "+f"(c[1]), "+f"(c[2]), "+f"(c[3])
                 : "r"(a[0]), "r"(a[1]), "r"(a[2]), "r"(a[3]), "r"(b0), "r"(b1));
}
__device__ __forceinline__ void mma16816z(float* c, const unsigned* a, unsigned b0, unsigned b1) {
    asm volatile("mma.sync.aligned.m16n8k16.row.col.f32.f16.f16.f32 "
                 "{%0,%1,%2,%3}, {%4,%5,%6,%7}, {%8,%9}, {%10,%11,%12,%13};\n"
                 : "=f"(c[0]), "=f"(c[1]), "=f"(c[2]), "=f"(c[3])
                 : "r"(a[0]), "r"(a[1]), "r"(a[2]), "r"(a[3]), "r"(b0), "r"(b1),
                   "f"(0.f), "f"(0.f), "f"(0.f), "f"(0.f));
}
// f16-accumulator QK MMA: D (f16x2 pair) = A*B, zero C.
__device__ __forceinline__ void mma16816zh(unsigned& c0, unsigned& c1,
                                           const unsigned* a, unsigned b0, unsigned b1) {
    asm volatile("mma.sync.aligned.m16n8k16.row.col.f16.f16.f16.f16 "
                 "{%0,%1}, {%2,%3,%4,%5}, {%6,%7}, {%8,%9};\n"
                 : "=r"(c0), "=r"(c1)
                 : "r"(a[0]), "r"(a[1]), "r"(a[2]), "r"(a[3]), "r"(b0), "r"(b1),
                   "r"(0u), "r"(0u));
}
__device__ __forceinline__ unsigned packh2(float x, float y) {
    __half2 h = __floats2half2_rn(x, y);
    return reinterpret_cast<unsigned&>(h);
}
__device__ __forceinline__ unsigned ex2h2(unsigned x) {
    unsigned r;
    asm volatile("ex2.approx.f16x2 %0, %1;\n" : "=r"(r) : "r"(x));
    return r;
}
__device__ __forceinline__ unsigned hadd2u(unsigned a, unsigned b) {
    __half2 r = __hadd2(reinterpret_cast<__half2&>(a), reinterpret_cast<__half2&>(b));
    return reinterpret_cast<unsigned&>(r);
}

// ---------------- fp16 conversion kernels ------------------------------------
__global__ __launch_bounds__(256) void conv_src_kernel(const float* __restrict__ in,
                                                       __half* __restrict__ out, int n) {
    int i = (blockIdx.x * 256 + threadIdx.x) * 4;
    if (i < n) {
        float4 v = *(const float4*)(in + i);
        *(__half2*)(out + i)     = __floats2half2_rn(v.x, v.y);
        *(__half2*)(out + i + 2) = __floats2half2_rn(v.z, v.w);
    }
}

__global__ __launch_bounds__(256) void conv_w_kernel(
    const float* wq, const float* wk, const float* wv, const float* wo,
    const float* w1, const float* w2,
    __half* oq, __half* ok, __half* ov, __half* oo, __half* o1, __half* o2)
{
    const float* in; __half* out; int n;
    switch (blockIdx.y) {
        case 0: in = wq; out = oq; n = DMODEL * DPROJ; break;
        case 1: in = wk; out = ok; n = DMODEL * DPROJ; break;
        case 2: in = wv; out = ov; n = DMODEL * DPROJ; break;
        case 3: in = wo; out = oo; n = DPROJ * DMODEL; break;
        case 4: in = w1; out = o1; n = DMODEL * DFF; break;
        default: in = w2; out = o2; n = DFF * DMODEL; break;
    }
    int i = (blockIdx.x * 256 + threadIdx.x) * 4;
    if (i < n) {
        float4 v = *(const float4*)(in + i);
        *(__half2*)(out + i)     = __floats2half2_rn(v.x, v.y);
        *(__half2*)(out + i + 2) = __floats2half2_rn(v.z, v.w);
    }
}

// ---------------- tensor-core GEMM (2-stage, static smem, BM templated) ------
#define ASTR 40   // A smem row stride in halves

template <int BM>
__device__ __forceinline__ void gemm_load_tile(
    unsigned aB, unsigned bB, const __half* __restrict__ A, const __half* __restrict__ B,
    int tid, int m0, int n0, int k0, int N, int K)
{
#pragma unroll
    for (int it = 0; it < BM / 64; ++it) {
        int c = tid + it * 256;
        int row = c >> 2, ch = c & 3;
        cp16(aB + row * (ASTR * 2) + ch * 16,
             A + (size_t)(m0 + row) * K + k0 + ch * 8);
    }
#pragma unroll
    for (int it = 0; it < 2; ++it) {
        int c = tid + it * 256;
        int k = c >> 4, ch = c & 15;
        cp16(bB + k * 256 + ((ch ^ (k & 7)) << 4),
             B + (size_t)(k0 + k) * N + n0 + ch * 8);
    }
    cp_commit();
}

template <int BM, int OUT_HALF, int RELU>
__device__ __forceinline__ void gemm_body(
    const __half* __restrict__ A, const __half* __restrict__ B,
    const float* __restrict__ bias, void* __restrict__ Cout, int N, int K)
{
    constexpr int MI = BM / 32;
    __shared__ __half sA[2][BM * ASTR];
    __shared__ __half sB[2][32 * 128];

    const int tid = threadIdx.x;
    const int lane = tid & 31;
    const int wid = tid >> 5;
    const int wm = (wid >> 2) * (BM / 2);
    const int wn = (wid & 3) * 32;
    const int m0 = blockIdx.y * BM;
    const int n0 = blockIdx.x * 128;

    unsigned aB[2] = { smem_u32(sA[0]), smem_u32(sA[1]) };
    unsigned bB[2] = { smem_u32(sB[0]), smem_u32(sB[1]) };

    float acc[MI][4][4] = {};

    const int KT = K >> 5;
    gemm_load_tile<BM>(aB[0], bB[0], A, B, tid, m0, n0, 0, N, K);

    const int lrow = lane & 15;
    const int lcol = (lane >> 4) * 8;

    for (int kt = 0; kt < KT; ++kt) {
        if (kt + 1 < KT) {
            gemm_load_tile<BM>(aB[(kt + 1) & 1], bB[(kt + 1) & 1], A, B, tid, m0, n0, (kt + 1) << 5, N, K);
            cp_wait1();
        } else {
            cp_wait0();
        }
        __syncthreads();
        const int buf = kt & 1;
#pragma unroll
        for (int s = 0; s < 2; ++s) {
            unsigned av[MI][4];
#pragma unroll
            for (int i = 0; i < MI; ++i) {
                unsigned addr = aB[buf] + (unsigned)((wm + i * 16 + lrow) * (ASTR * 2) + (s * 16 + lcol) * 2);
                ldmx4(av[i][0], av[i][1], av[i][2], av[i][3], addr);
            }
#pragma unroll
            for (int p = 0; p < 2; ++p) {
                const int mi = lane >> 3, r = lane & 7;
                const int krow = s * 16 + (mi & 1) * 8 + r;
                const int nch = (wn >> 3) + p * 2 + (mi >> 1);
                unsigned addr = bB[buf] + (unsigned)(krow * 256 + ((nch ^ (krow & 7)) << 4));
                unsigned b0, b1, b2, b3;
                ldmx4t(b0, b1, b2, b3, addr);
#pragma unroll
                for (int i = 0; i < MI; ++i) {
                    mma16816(acc[i][2 * p + 0], av[i], b0, b1);
                    mma16816(acc[i][2 * p + 1], av[i], b2, b3);
                }
            }
        }
        __syncthreads();
    }

#pragma unroll
    for (int i = 0; i < MI; ++i) {
        const int row = m0 + wm + i * 16 + (lane >> 2);
#pragma unroll
        for (int j = 0; j < 4; ++j) {
            const int col = n0 + wn + j * 8 + (lane & 3) * 2;
            float c0 = acc[i][j][0], c1 = acc[i][j][1], c2 = acc[i][j][2], c3 = acc[i][j][3];
            if (bias) {
                float2 bv = *(const float2*)&bias[col];
                c0 += bv.x; c1 += bv.y; c2 += bv.x; c3 += bv.y;
            }
            if (RELU) {
                c0 = fmaxf(c0, 0.f); c1 = fmaxf(c1, 0.f);
                c2 = fmaxf(c2, 0.f); c3 = fmaxf(c3, 0.f);
            }
            if (OUT_HALF) {
                __half* Ch = (__half*)Cout;
                *(__half2*)&Ch[(size_t)row * N + col]       = __floats2half2_rn(c0, c1);
                *(__half2*)&Ch[(size_t)(row + 8) * N + col] = __floats2half2_rn(c2, c3);
            } else {
                float* Cf = (float*)Cout;
                *(float2*)&Cf[(size_t)row * N + col]       = make_float2(c0, c1);
                *(float2*)&Cf[(size_t)(row + 8) * N + col] = make_float2(c2, c3);
            }
        }
    }
}

template <int OUT_HALF, int RELU>
__global__ __launch_bounds__(256) void gemm_k(
    const __half* __restrict__ A, const __half* __restrict__ B,
    const float* __restrict__ bias, void* __restrict__ C, int N, int K)
{
    gemm_body<128, OUT_HALF, RELU>(A, B, bias, C, N, K);
}

__global__ __launch_bounds__(256) void qkv_gemm_k(
    const __half* __restrict__ A,
    const __half* __restrict__ Bq, const __half* __restrict__ Bk, const __half* __restrict__ Bv,
    const float* __restrict__ bq, const float* __restrict__ bk, const float* __restrict__ bv,
    __half* __restrict__ oq, __half* __restrict__ ok, __half* __restrict__ ov)
{
    const __half* B; const float* bias; __half* out;
    switch (blockIdx.z) {
        case 0:  B = Bq; bias = bq; out = oq; break;
        case 1:  B = Bk; bias = bk; out = ok; break;
        default: B = Bv; bias = bv; out = ov; break;
    }
    gemm_body<64, 1, 0>(A, B, bias, out, DPROJ, DMODEL);
}

// ---------------- GEMM + residual(fp16) + LayerNorm fused (N=256) ------------
__device__ __forceinline__ void gemmln_load_tile(
    unsigned aB, unsigned bB, const __half* __restrict__ A, const __half* __restrict__ B,
    int tid, int m0, int k0, int K)
{
    {
        int row = tid >> 2, ch = tid & 3;
        cp16(aB + row * (ASTR * 2) + ch * 16,
             A + (size_t)(m0 + row) * K + k0 + ch * 8);
    }
#pragma unroll
    for (int it = 0; it < 4; ++it) {
        int c = tid + it * 256;
        int k = c >> 5, ch = c & 31;
        cp16(bB + k * 512 + ((ch ^ (k & 7)) << 4),
             B + (size_t)(k0 + k) * 256 + ch * 8);
    }
    cp_commit();
}

template <int HAS_BIAS, int OUT32, int OUT16>
__global__ __launch_bounds__(256) void gemm_ln_k(
    const __half* __restrict__ A, const __half* __restrict__ B,
    const float* __restrict__ bias, const __half* __restrict__ res,
    const float* __restrict__ g, const float* __restrict__ be,
    float* __restrict__ out, __half* __restrict__ out16, int K)
{
    __shared__ __half sA[2][64 * ASTR];
    __shared__ __half sB[2][32 * 256];
    __shared__ float sS[64][2];
    __shared__ float sQ[64][2];
    __shared__ float sG[256];
    __shared__ float sBe[256];
    __shared__ float sBias[256];

    const int tid = threadIdx.x;
    const int lane = tid & 31;
    const int wid = tid >> 5;
    const int mwarp = wid >> 1;
    const int nwarp = wid & 1;
    const int moff = mwarp * 16;
    const int m0 = blockIdx.x * 64;

    sG[tid] = g[tid];
    sBe[tid] = be[tid];
    if (HAS_BIAS) sBias[tid] = bias[tid];

    unsigned aB[2] = { smem_u32(sA[0]), smem_u32(sA[1]) };
    unsigned bB[2] = { smem_u32(sB[0]), smem_u32(sB[1]) };

    float acc[16][4] = {};

    const int KT = K >> 5;
    gemmln_load_tile(aB[0], bB[0], A, B, tid, m0, 0, K);

    const int lrow = lane & 15;
    const int lcol = (lane >> 4) * 8;
    const int mi = lane >> 3, r = lane & 7;

    for (int kt = 0; kt < KT; ++kt) {
        if (kt + 1 < KT) {
            gemmln_load_tile(aB[(kt + 1) & 1], bB[(kt + 1) & 1], A, B, tid, m0, (kt + 1) << 5, K);
            cp_wait1();
        } else {
            cp_wait0();
        }
        __syncthreads();
        const int buf = kt & 1;
#pragma unroll
        for (int s = 0; s < 2; ++s) {
            unsigned av[4];
            {
                unsigned addr = aB[buf] + (unsigned)((moff + lrow) * (ASTR * 2) + (s * 16 + lcol) * 2);
                ldmx4(av[0], av[1], av[2], av[3], addr);
            }
            const int krow = s * 16 + (mi & 1) * 8 + r;
#pragma unroll
            for (int p = 0; p < 8; ++p) {
                const int nch = nwarp * 16 + p * 2 + (mi >> 1);
                unsigned addr = bB[buf] + (unsigned)(krow * 512 + ((nch ^ (krow & 7)) << 4));
                unsigned b0, b1, b2, b3;
                ldmx4t(b0, b1, b2, b3, addr);
                mma16816(acc[2 * p + 0], av, b0, b1);
                mma16816(acc[2 * p + 1], av, b2, b3);
            }
        }
        __syncthreads();
    }

    const int ra = m0 + moff + (lane >> 2);
    const int rb = ra + 8;
    const int cbase = nwarp * 128 + (lane & 3) * 2;

    float sumA = 0.f, sqA = 0.f, sumB = 0.f, sqB = 0.f;
#pragma unroll
    for (int j = 0; j < 16; ++j) {
        const int col = cbase + j * 8;
        float2 rA = __half22float2(*(const __half2*)&res[(size_t)ra * 256 + col]);
        float2 rB = __half22float2(*(const __half2*)&res[(size_t)rb * 256 + col]);
        float b0v = 0.f, b1v = 0.f;
        if (HAS_BIAS) { b0v = sBias[col]; b1v = sBias[col + 1]; }
        float v0 = acc[j][0] + b0v + rA.x;
        float v1 = acc[j][1] + b1v + rA.y;
        float v2 = acc[j][2] + b0v + rB.x;
        float v3 = acc[j][3] + b1v + rB.y;
        acc[j][0] = v0; acc[j][1] = v1; acc[j][2] = v2; acc[j][3] = v3;
        sumA += v0 + v1; sqA += v0 * v0 + v1 * v1;
        sumB += v2 + v3; sqB += v2 * v2 + v3 * v3;
    }
    sumA += __shfl_xor_sync(0xffffffffu, sumA, 1);
    sumA += __shfl_xor_sync(0xffffffffu, sumA, 2);
    sqA  += __shfl_xor_sync(0xffffffffu, sqA, 1);
    sqA  += __shfl_xor_sync(0xffffffffu, sqA, 2);
    sumB += __shfl_xor_sync(0xffffffffu, sumB, 1);
    sumB += __shfl_xor_sync(0xffffffffu, sumB, 2);
    sqB  += __shfl_xor_sync(0xffffffffu, sqB, 1);
    sqB  += __shfl_xor_sync(0xffffffffu, sqB, 2);
    if ((lane & 3) == 0) {
        const int rl = moff + (lane >> 2);
        sS[rl][nwarp] = sumA; sQ[rl][nwarp] = sqA;
        sS[rl + 8][nwarp] = sumB; sQ[rl + 8][nwarp] = sqB;
    }
    __syncthreads();

    const int rlA = moff + (lane >> 2);
    const float totSA = sS[rlA][0] + sS[rlA][1];
    const float totQA = sQ[rlA][0] + sQ[rlA][1];
    const float muA = totSA * (1.0f / 256.0f);
    const float rsA = rsqrtf(totQA * (1.0f / 256.0f) - muA * muA + 1e-5f);
    const float totSB = sS[rlA + 8][0] + sS[rlA + 8][1];
    const float totQB = sQ[rlA + 8][0] + sQ[rlA + 8][1];
    const float muB = totSB * (1.0f / 256.0f);
    const float rsB = rsqrtf(totQB * (1.0f / 256.0f) - muB * muB + 1e-5f);

#pragma unroll
    for (int j = 0; j < 16; ++j) {
        const int col = cbase + j * 8;
        const float g0 = sG[col], g1 = sG[col + 1];
        const float e0 = sBe[col], e1 = sBe[col + 1];
        float o0 = (acc[j][0] - muA) * rsA * g0 + e0;
        float o1 = (acc[j][1] - muA) * rsA * g1 + e1;
        float o2 = (acc[j][2] - muB) * rsB * g0 + e0;
        float o3 = (acc[j][3] - muB) * rsB * g1 + e1;
        if (OUT32) {
            *(float2*)&out[(size_t)ra * 256 + col] = make_float2(o0, o1);
            *(float2*)&out[(size_t)rb * 256 + col] = make_float2(o2, o3);
        }
        if (OUT16) {
            *(__half2*)&out16[(size_t)ra * 256 + col] = __floats2half2_rn(o0, o1);
            *(__half2*)&out16[(size_t)rb * 256 + col] = __floats2half2_rn(o2, o3);
        }
    }
}

// ---------------- flash attention: 32 queries/warp (r12 proven body) ---------
#define KSTR 24

__device__ __forceinline__ void attn_load_kv(
    unsigned kB, unsigned vB, const __half* __restrict__ k, const __half* __restrict__ v,
    int tid, int kstart, int b, int h)
{
    const int row = tid >> 1, ch = tid & 1;
    const size_t g = ((size_t)(kstart + row) * BATCH + b) * DPROJ + h * DH + ch * 8;
    cp16(kB + row * (KSTR * 2) + ch * 16, k + g);
    cp16(vB + row * (KSTR * 2) + ch * 16, v + g);
}

__global__ __launch_bounds__(256) void attn_kernel(
    const __half* __restrict__ q, const __half* __restrict__ k,
    const __half* __restrict__ v, __half* __restrict__ ctx)
{
    __shared__ __half sQ[256 * KSTR];
    __shared__ __half sK[2][128 * KSTR];
    __shared__ __half sV[2][128 * KSTR];

    const int tid = threadIdx.x;
    const int lane = tid & 31;
    const int wid = tid >> 5;
    const int qt = blockIdx.x;
    const int bh = blockIdx.y;
    const int b = bh >> 3, h = bh & 7;
    const int q0 = qt * 256;
    const int wq = wid * 32;

    unsigned qB = smem_u32(sQ);
    unsigned kB[2] = { smem_u32(sK[0]), smem_u32(sK[1]) };
    unsigned vB[2] = { smem_u32(sV[0]), smem_u32(sV[1]) };

    const unsigned bones = (lane < 4) ? 0x3C003C00u : 0u;

    {
        const size_t g = ((size_t)(q0 + tid) * BATCH + b) * DPROJ + h * DH;
        cp16(qB + tid * (KSTR * 2), q + g);
        cp16(qB + tid * (KSTR * 2) + 16, q + g + 8);
    }
    attn_load_kv(kB[0], vB[0], k, v, tid, 0, b, h);
    cp_commit();

    float o00[4] = {}, o01[4] = {}, o10[4] = {}, o11[4] = {};
    float ol0[4] = {}, ol1[4] = {};
    unsigned qa0[4], qa1[4];

    const int mi = lane >> 3, r = lane & 7;
    const unsigned vrow_off = (unsigned)(((mi & 1) * 8 + r) * (KSTR * 2) + (mi >> 1) * 16);

    for (int kt = 0; kt < SEQ / 128; ++kt) {
        if (kt + 1 < SEQ / 128) {
            attn_load_kv(kB[(kt + 1) & 1], vB[(kt + 1) & 1], k, v, tid, (kt + 1) * 128, b, h);
            cp_commit();
            cp_wait1();
        } else {
            cp_wait0();
        }
        __syncthreads();
        const int buf = kt & 1;

        if (kt == 0) {
            const __half2 ce2 = __float2half2_rn(0.25f * 1.44269504088896f);
            unsigned base = qB + (unsigned)((wq + (lane >> 2)) * (KSTR * 2) + (lane & 3) * 4);
#pragma unroll
            for (int m = 0; m < 2; ++m) {
                unsigned* qa = m ? qa1 : qa0;
                unsigned bb = base + (unsigned)(m * 16 * (KSTR * 2));
                qa[0] = lds_u32(bb);
                qa[1] = lds_u32(bb + 8 * (KSTR * 2));
                qa[2] = lds_u32(bb + 16);
                qa[3] = lds_u32(bb + 8 * (KSTR * 2) + 16);
#pragma unroll
                for (int i = 0; i < 4; ++i) {
                    __half2 t = __hmul2(reinterpret_cast<__half2&>(qa[i]), ce2);
                    qa[i] = reinterpret_cast<unsigned&>(t);
                }
            }
        }

        const unsigned kfrag = kB[buf] + (unsigned)((lane >> 2) * (KSTR * 2) + (lane & 3) * 4);
        unsigned ps0[4] = {0u, 0u, 0u, 0u};
        unsigned ps1[4] = {0u, 0u, 0u, 0u};

#pragma unroll
        for (int s = 0; s < 8; ++s) {
            unsigned kb0 = kfrag + (unsigned)((s * 16) * (KSTR * 2));
            unsigned kb1 = kb0 + (unsigned)(8 * (KSTR * 2));
            unsigned k00 = lds_u32(kb0), k01 = lds_u32(kb0 + 16);
            unsigned k10 = lds_u32(kb1), k11 = lds_u32(kb1 + 16);

            unsigned sa0_0, sa0_1, sa1_0, sa1_1;
            unsigned sb0_0, sb0_1, sb1_0, sb1_1;
            mma16816zh(sa0_0, sa0_1, qa0, k00, k01);
            mma16816zh(sa1_0, sa1_1, qa0, k10, k11);
            mma16816zh(sb0_0, sb0_1, qa1, k00, k01);
            mma16816zh(sb1_0, sb1_1, qa1, k10, k11);

            unsigned pa[4], pb[4];
            pa[0] = ex2h2(sa0_0);
            pa[1] = ex2h2(sa0_1);
            pa[2] = ex2h2(sa1_0);
            pa[3] = ex2h2(sa1_1);
            pb[0] = ex2h2(sb0_0);
            pb[1] = ex2h2(sb0_1);
            pb[2] = ex2h2(sb1_0);
            pb[3] = ex2h2(sb1_1);

            ps0[0] = hadd2u(ps0[0], pa[0]); ps0[1] = hadd2u(ps0[1], pa[1]);
            ps0[2] = hadd2u(ps0[2], pa[2]); ps0[3] = hadd2u(ps0[3], pa[3]);
            ps1[0] = hadd2u(ps1[0], pb[0]); ps1[1] = hadd2u(ps1[1], pb[1]);
            ps1[2] = hadd2u(ps1[2], pb[2]); ps1[3] = hadd2u(ps1[3], pb[3]);

            unsigned addr = vB[buf] + (unsigned)(s * 16 * (KSTR * 2)) + vrow_off;
            unsigned vb0, vb1, vb2, vb3;
            ldmx4t(vb0, vb1, vb2, vb3, addr);
            mma16816(o00, pa, vb0, vb1);
            mma16816(o01, pa, vb2, vb3);
            mma16816(o10, pb, vb0, vb1);
            mma16816(o11, pb, vb2, vb3);
        }
        mma16816(ol0, ps0, bones, bones);
        mma16816(ol1, ps1, bones, bones);
        __syncthreads();
    }

    float l00 = __shfl_sync(0xffffffffu, ol0[0], lane & 28);
    float l01 = __shfl_sync(0xffffffffu, ol0[2], lane & 28);
    float l10 = __shfl_sync(0xffffffffu, ol1[0], lane & 28);
    float l11 = __shfl_sync(0xffffffffu, ol1[2], lane & 28);
    const float i00 = 1.f / l00, i01 = 1.f / l01;
    const float i10 = 1.f / l10, i11 = 1.f / l11;

    const int rbase = q0 + wq + (lane >> 2);
    const int col0 = h * DH + (lane & 3) * 2;
    const int col1 = col0 + 8;
    *(__half2*)&ctx[((size_t)rbase * BATCH + b) * DPROJ + col0] =
        __floats2half2_rn(o00[0] * i00, o00[1] * i00);
    *(__half2*)&ctx[((size_t)(rbase + 8) * BATCH + b) * DPROJ + col0] =
        __floats2half2_rn(o00[2] * i01, o00[3] * i01);
    *(__half2*)&ctx[((size_t)rbase * BATCH + b) * DPROJ + col1] =
        __floats2half2_rn(o01[0] * i00, o01[1] * i00);
    *(__half2*)&ctx[((size_t)(rbase + 8) * BATCH + b) * DPROJ + col1] =
        __floats2half2_rn(o01[2] * i01, o01[3] * i01);
    *(__half2*)&ctx[((size_t)(rbase + 16) * BATCH + b) * DPROJ + col0] =
        __floats2half2_rn(o10[0] * i10, o10[1] * i10);
    *(__half2*)&ctx[((size_t)(rbase + 24) * BATCH + b) * DPROJ + col0] =
        __floats2half2_rn(o10[2] * i11, o10[3] * i11);
    *(__half2*)&ctx[((size_t)(rbase + 16) * BATCH + b) * DPROJ + col1] =
        __floats2half2_rn(o11[0] * i10, o11[1] * i10);
    *(__half2*)&ctx[((size_t)(rbase + 24) * BATCH + b) * DPROJ + col1] =
        __floats2half2_rn(o11[2] * i11, o11[3] * i11);
}

// ---------------- launch ----------------------------------------------------
extern "C" void kernel_launch(void* const* d_in, const int* in_sizes, int n_in,
                              void* d_out, int out_size)
{
    const float* src   = (const float*)d_in[0];
    const float* Wq    = (const float*)d_in[1];
    const float* bq    = (const float*)d_in[2];
    const float* Wk    = (const float*)d_in[3];
    const float* bk    = (const float*)d_in[4];
    const float* Wv    = (const float*)d_in[5];
    const float* bv    = (const float*)d_in[6];
    const float* Wo    = (const float*)d_in[7];
    const float* ln1_g = (const float*)d_in[8];
    const float* ln1_b = (const float*)d_in[9];
    const float* W1    = (const float*)d_in[10];
    const float* b1    = (const float*)d_in[11];
    const float* W2    = (const float*)d_in[12];
    const float* b2    = (const float*)d_in[13];
    const float* ln2_g = (const float*)d_in[14];
    const float* ln2_b = (const float*)d_in[15];
    float* out = (float*)d_out;

    __half *p_q, *p_k, *p_v, *p_ctx, *p_h, *p_x16, *p_src16;
    __half *p_wq, *p_wk, *p_wv, *p_wo, *p_w1, *p_w2;
    cudaGetSymbolAddress((void**)&p_q, g_q16);
    cudaGetSymbolAddress((void**)&p_k, g_k16);
    cudaGetSymbolAddress((void**)&p_v, g_v16);
    cudaGetSymbolAddress((void**)&p_ctx, g_ctx16);
    cudaGetSymbolAddress((void**)&p_h, g_h16);
    cudaGetSymbolAddress((void**)&p_x16, g_x16);
    cudaGetSymbolAddress((void**)&p_src16, g_src16);
    cudaGetSymbolAddress((void**)&p_wq, g_wq16);
    cudaGetSymbolAddress((void**)&p_wk, g_wk16);
    cudaGetSymbolAddress((void**)&p_wv, g_wv16);
    cudaGetSymbolAddress((void**)&p_wo, g_wo16);
    cudaGetSymbolAddress((void**)&p_w1, g_w116);
    cudaGetSymbolAddress((void**)&p_w2, g_w216);

    // 0. fp16 conversions
    conv_w_kernel<<<dim3(256, 6), 256>>>(Wq, Wk, Wv, Wo, W1, W2,
                                         p_wq, p_wk, p_wv, p_wo, p_w1, p_w2);
    conv_src_kernel<<<(MROWS * DMODEL) / 1024, 256>>>(src, p_src16, MROWS * DMODEL);

    // 1. QKV projections (BM=64 tiles)
    {
        dim3 grid(DPROJ / 128, MROWS / 64, 3);
        qkv_gemm_k<<<grid, 256>>>(p_src16, p_wq, p_wk, p_wv, bq, bk, bv, p_q, p_k, p_v);
    }
    // 2. attention -> ctx fp16 (256 queries per CTA)
    {
        dim3 grid(SEQ / 256, BATCH * NHEADS);
        attn_kernel<<<grid, 256>>>(p_q, p_k, p_v, p_ctx);
    }
    // 3+4. x16 = LN1(src16 + ctx@Wo)  [fp16 residual in, fp16 out only]
    gemm_ln_k<0, 0, 1><<<MROWS / 64, 256>>>(p_ctx, p_wo, nullptr, p_src16,
                                            ln1_g, ln1_b, nullptr, p_x16, DPROJ);
    // 5. h = relu(x @ W1 + b1), fp16 out
    {
        dim3 grid(DFF / 128, MROWS / 128);
        gemm_k<1, 1><<<grid, 256>>>(p_x16, p_w1, b1, p_h, DFF, DMODEL);
    }
    // 6+7. out = LN2(x16 + h@W2 + b2)  [fp16 residual in, fp32 out]
    gemm_ln_k<1, 1, 0><<<MROWS / 64, 256>>>(p_h, p_w2, b2, p_x16,
                                            ln2_g, ln2_b, out, nullptr, DFF);
}